// round 1
// baseline (speedup 1.0000x reference)
#include <cuda_runtime.h>

// Problem shape (fixed by the dataset)
#define B_DIM 128
#define N_DIM 131072

// Scratch: per-row weight sums (device global — no allocation allowed)
__device__ float g_row_sums[B_DIM];

constexpr int THREADS    = 256;
constexpr int PER_THREAD = 8;                          // float4s per thread
constexpr int CHUNK      = THREADS * 4 * PER_THREAD;   // 8192 elements per block
constexpr int BLOCKS_X   = N_DIM / CHUNK;              // 16 blocks per row

__global__ void zero_sums_kernel() {
    if (threadIdx.x < B_DIM) g_row_sums[threadIdx.x] = 0.0f;
}

__device__ __forceinline__ float transition_likelihood(
    float x, float nz, float cterm, float ob, float pwv, float& w_out)
{
    // UNGM transition: x/2 + 25*x/(x^2+1) + 8*cos(1.2*t) + noise*sqrt(10)
    float mean = fmaf(x, 0.5f, 25.0f * __fdividef(x, fmaf(x, x, 1.0f))) + cterm;
    float np   = fmaf(nz, 3.16227766f, mean);          // sqrt(10) as f32
    // log N(obs; np^2/20, 1)
    float om   = np * np * 0.05f;
    float d    = ob - om;
    float lp   = fmaf(-0.5f * d, d, -0.9189385332f);   // -0.5*log(2*pi)
    w_out      = pwv * __expf(lp);
    return np;
}

__global__ void __launch_bounds__(THREADS)
pf_step_kernel(const float* __restrict__ particles,
               const float* __restrict__ pw,
               const float* __restrict__ obs,
               const float* __restrict__ noise,
               const int*   __restrict__ tstep,
               float* __restrict__ out_np,
               float* __restrict__ out_w)
{
    const int b = blockIdx.y;
    const long base = (long)b * N_DIM + (long)blockIdx.x * CHUNK;

    const float t     = (float)__ldg(tstep);
    const float cterm = 8.0f * cosf(1.2f * t);
    const float ob    = __ldg(obs + b);

    const float4* p4  = (const float4*)(particles + base);
    const float4* n4  = (const float4*)(noise + base);
    const float4* w4  = (const float4*)(pw + base);
    float4* onp4      = (float4*)(out_np + base);
    float4* ow4       = (float4*)(out_w + base);

    float lsum = 0.0f;

    #pragma unroll
    for (int i = 0; i < PER_THREAD; i++) {
        const int off = i * THREADS + threadIdx.x;
        float4 x  = p4[off];
        float4 nz = n4[off];
        float4 pv = w4[off];
        float4 np_, wv;
        np_.x = transition_likelihood(x.x, nz.x, cterm, ob, pv.x, wv.x);
        np_.y = transition_likelihood(x.y, nz.y, cterm, ob, pv.y, wv.y);
        np_.z = transition_likelihood(x.z, nz.z, cterm, ob, pv.z, wv.z);
        np_.w = transition_likelihood(x.w, nz.w, cterm, ob, pv.w, wv.w);
        onp4[off] = np_;
        ow4[off]  = wv;
        lsum += (wv.x + wv.y) + (wv.z + wv.w);
    }

    // Block reduction of lsum -> one atomicAdd per block
    __shared__ float red[THREADS / 32];
    #pragma unroll
    for (int s = 16; s > 0; s >>= 1)
        lsum += __shfl_xor_sync(0xFFFFFFFFu, lsum, s);
    const int lane = threadIdx.x & 31;
    const int wid  = threadIdx.x >> 5;
    if (lane == 0) red[wid] = lsum;
    __syncthreads();
    if (wid == 0) {
        float v = (lane < THREADS / 32) ? red[lane] : 0.0f;
        #pragma unroll
        for (int s = 4; s > 0; s >>= 1)
            v += __shfl_xor_sync(0xFFFFFFFFu, v, s);
        if (lane == 0) atomicAdd(&g_row_sums[b], v);
    }
}

__global__ void __launch_bounds__(THREADS)
normalize_kernel(float* __restrict__ out_w)
{
    const int b = blockIdx.y;
    const float inv = __frcp_rn(g_row_sums[b]);
    const long base = (long)b * N_DIM + (long)blockIdx.x * CHUNK;
    float4* w4 = (float4*)(out_w + base);

    #pragma unroll
    for (int i = 0; i < PER_THREAD; i++) {
        const int off = i * THREADS + threadIdx.x;
        float4 v = w4[off];
        v.x *= inv; v.y *= inv; v.z *= inv; v.w *= inv;
        w4[off] = v;
    }
}

extern "C" void kernel_launch(void* const* d_in, const int* in_sizes, int n_in,
                              void* d_out, int out_size)
{
    const float* particles = (const float*)d_in[0];   // [B, N, 1]
    const float* pw        = (const float*)d_in[1];   // [B, N]
    const float* obs       = (const float*)d_in[2];   // [B, 1]
    const float* noise     = (const float*)d_in[3];   // [B, N, 1]
    // d_in[4] = uniforms — dead code in the reference (resample output unused)
    const int*   tstep     = (const int*)d_in[5];     // scalar

    float* out_np = (float*)d_out;                    // [B, N, 1]
    float* out_w  = out_np + (size_t)B_DIM * N_DIM;   // [B, N]

    dim3 grid(BLOCKS_X, B_DIM);

    zero_sums_kernel<<<1, B_DIM>>>();
    pf_step_kernel<<<grid, THREADS>>>(particles, pw, obs, noise, tstep,
                                      out_np, out_w);
    normalize_kernel<<<grid, THREADS>>>(out_w);
}